// round 5
// baseline (speedup 1.0000x reference)
#include <cuda_runtime.h>
#include <cuda_bf16.h>
#include <math.h>
#include <stdint.h>

#define NS 100000
#define NI 20000
#define D  128
#define L  2
#define E1 600000
#define E2 500000

// ---------------- scratch (static device globals: allocation-free) ----------------
__device__ float g_agg_s[(size_t)NS * D];
__device__ float g_agg_i[(size_t)NI * D];
__device__ float g_h   [(size_t)NS * D];
__device__ float g_xs  [(size_t)NS * D];
__device__ float g_xi  [(size_t)NI * D];
__device__ float g_item[(size_t)NI * D];
__device__ float g_bn[2 * D];
__device__ float g_bnscale[D];
__device__ float g_bnshift[D];
// packed weights: 10 matrices (2 layers x 5): hi image (16384 bf16) + lo image (16384 bf16)
__device__ __nv_bfloat16 g_wpack[10 * 32768];
// CSR structures
__device__ int g_deg[NS + 2];
__device__ int g_bsum[128];
__device__ int g_rp_resp[NI + 1];
__device__ int g_rp_rev[NS + 1];
__device__ int g_rp_prec[NS + 1];
__device__ int g_col_resp[E1];
__device__ int g_col_rev[E1];
__device__ int g_col_prec[E2];

// ---------------- smem swizzle: 128 rows x 256B, 16B chunks XOR'd by row ----------------
__device__ __forceinline__ uint32_t sw_off(int row, int k) {
    return (uint32_t)(row * 256 + (((k >> 3) ^ (row & 7)) << 4) + ((k & 7) << 1));
}

__device__ __forceinline__ uint32_t s2u(const void* p) {
    uint32_t a;
    asm("{ .reg .u64 t; cvta.to.shared.u64 t, %1; cvt.u32.u64 %0, t; }" : "=r"(a) : "l"(p));
    return a;
}

__device__ __forceinline__ void ldsm4(uint32_t& r0, uint32_t& r1, uint32_t& r2, uint32_t& r3,
                                      uint32_t addr) {
    asm volatile("ldmatrix.sync.aligned.m8n8.x4.shared.b16 {%0,%1,%2,%3}, [%4];"
                 : "=r"(r0), "=r"(r1), "=r"(r2), "=r"(r3) : "r"(addr));
}

__device__ __forceinline__ void mma16816(float* c, uint32_t a0, uint32_t a1, uint32_t a2,
                                         uint32_t a3, uint32_t b0, uint32_t b1) {
    asm volatile("mma.sync.aligned.m16n8k16.row.col.f32.bf16.bf16.f32 "
                 "{%0,%1,%2,%3}, {%4,%5,%6,%7}, {%8,%9}, {%0,%1,%2,%3};"
                 : "+f"(c[0]), "+f"(c[1]), "+f"(c[2]), "+f"(c[3])
                 : "r"(a0), "r"(a1), "r"(a2), "r"(a3), "r"(b0), "r"(b1));
}

__device__ __forceinline__ void cpasync16(uint32_t s, const void* g) {
    asm volatile("cp.async.cg.shared.global [%0], [%1], 16;" :: "r"(s), "l"(g));
}

// ================= utility kernels =================
__global__ void zero_kernel(float4* __restrict__ p, int n4) {
    int i = blockIdx.x * blockDim.x + threadIdx.x;
    if (i < n4) p[i] = make_float4(0.f, 0.f, 0.f, 0.f);
}
__global__ void zero_int(int* __restrict__ p, int n) {
    int i = blockIdx.x * blockDim.x + threadIdx.x;
    if (i < n) p[i] = 0;
}

// ================= CSR build =================
__global__ void hist_kernel(const int* __restrict__ dst, int E, int* __restrict__ deg) {
    int e = blockIdx.x * blockDim.x + threadIdx.x;
    if (e < E) atomicAdd(&deg[dst[e]], 1);
}

// scan stage 1: per-1024 block sums (256 thr x 4 contiguous elems)
__global__ void scan_sum(const int* __restrict__ deg, int* __restrict__ bsum, int M) {
    __shared__ int wsum[8];
    int t = threadIdx.x;
    int base = blockIdx.x * 1024 + t * 4;
    int s = 0;
#pragma unroll
    for (int j = 0; j < 4; ++j) s += (base + j < M) ? deg[base + j] : 0;
#pragma unroll
    for (int o = 16; o > 0; o >>= 1) s += __shfl_down_sync(0xFFFFFFFFu, s, o);
    if ((t & 31) == 0) wsum[t >> 5] = s;
    __syncthreads();
    if (t == 0) {
        int r = 0;
#pragma unroll
        for (int w = 0; w < 8; ++w) r += wsum[w];
        bsum[blockIdx.x] = r;
    }
}

// scan stage 2: serial exclusive scan of block sums (nb <= 98)
__global__ void scan_offsets(int* __restrict__ bsum, int nb) {
    if (threadIdx.x == 0 && blockIdx.x == 0) {
        int r = 0;
        for (int b = 0; b < nb; ++b) { int x = bsum[b]; bsum[b] = r; r += x; }
    }
}

// scan stage 3: per-block exclusive scan + block offset -> row_ptr
__global__ void scan_block(const int* __restrict__ deg, const int* __restrict__ bsum,
                           int* __restrict__ rp, int M) {
    __shared__ int wsum[8];
    int t = threadIdx.x, lane = t & 31, wid = t >> 5;
    int base = blockIdx.x * 1024 + t * 4;
    int v[4];
#pragma unroll
    for (int j = 0; j < 4; ++j) v[j] = (base + j < M) ? deg[base + j] : 0;
    int tsum = v[0] + v[1] + v[2] + v[3];
    int incl = tsum;
#pragma unroll
    for (int o = 1; o < 32; o <<= 1) {
        int n = __shfl_up_sync(0xFFFFFFFFu, incl, o);
        if (lane >= o) incl += n;
    }
    if (lane == 31) wsum[wid] = incl;
    __syncthreads();
    if (t == 0) {
        int r = 0;
#pragma unroll
        for (int w = 0; w < 8; ++w) { int x = wsum[w]; wsum[w] = r; r += x; }
    }
    __syncthreads();
    int run = incl - tsum + wsum[wid] + bsum[blockIdx.x];
#pragma unroll
    for (int j = 0; j < 4; ++j) {
        if (base + j < M) { rp[base + j] = run; run += v[j]; }
    }
}

__global__ void fill_kernel(const int* __restrict__ src, const int* __restrict__ dst, int E,
                            const int* __restrict__ rp, int* __restrict__ fillc,
                            int* __restrict__ col) {
    int e = blockIdx.x * blockDim.x + threadIdx.x;
    if (e >= E) return;
    int d = dst[e];
    int pos = rp[d] + atomicAdd(&fillc[d], 1);
    col[pos] = src[e];
}

// ================= CSR aggregation: warp per destination row =================
// mode 0: out[r] = (1/max(deg,1)) * sum_{i} X[col[i]]
// mode 1: out[r] += coef * sum_{i} X[col[i]]
__global__ void agg_csr(const float* __restrict__ X, const int* __restrict__ rp,
                        const int* __restrict__ col, int N, int mode, float coef,
                        float* __restrict__ out) {
    int r = (int)((blockIdx.x * (unsigned)blockDim.x + threadIdx.x) >> 5);
    int lane = threadIdx.x & 31;
    if (r >= N) return;
    int beg = rp[r], end = rp[r + 1];
    float4 acc = make_float4(0.f, 0.f, 0.f, 0.f);
    int i = beg;
    int s_next = (i < end) ? __ldg(col + i) : 0;
    while (i < end) {
        int s = s_next;
        ++i;
        s_next = (i < end) ? __ldg(col + i) : 0;
        float4 v = __ldg((const float4*)(X + (size_t)s * D + lane * 4));
        acc.x += v.x; acc.y += v.y; acc.z += v.z; acc.w += v.w;
    }
    float sc = (mode == 0) ? (1.f / fmaxf((float)(end - beg), 1.f)) : coef;
    acc.x *= sc; acc.y *= sc; acc.z *= sc; acc.w *= sc;
    float* op = out + (size_t)r * D + lane * 4;
    if (mode == 1) {
        float4 o = *(const float4*)op;
        acc.x += o.x; acc.y += o.y; acc.z += o.z; acc.w += o.w;
    }
    *(float4*)op = acc;
}

// Pack all 10 weight matrices into bf16 hi/lo swizzled images ([n][k] rows of 256B).
__global__ void pack_w(const float* __restrict__ Wl_ri, const float* __restrict__ Wr_ri,
                       const float* __restrict__ Wl_rs, const float* __restrict__ Wr_rs,
                       const float* __restrict__ W_p, __nv_bfloat16* __restrict__ dst) {
    int gid = blockIdx.x * blockDim.x + threadIdx.x;
    if (gid >= 10 * 16384) return;
    int mid = gid >> 14;
    int idx = gid & 16383;
    int l = mid / 5, which = mid % 5;
    const float* src;
    switch (which) {
        case 0: src = Wl_ri; break;
        case 1: src = Wr_ri; break;
        case 2: src = Wl_rs; break;
        case 3: src = Wr_rs; break;
        default: src = W_p; break;
    }
    float a = src[(size_t)l * 16384 + idx];
    int n = idx >> 7, k = idx & 127;
    __nv_bfloat16 hi = __float2bfloat16(a);
    __nv_bfloat16 lo = __float2bfloat16(a - __bfloat162float(hi));
    uint32_t off = sw_off(n, k) >> 1;
    dst[(size_t)mid * 32768 + off] = hi;
    dst[(size_t)mid * 32768 + 16384 + off] = lo;
}

// ================= HMMA fused GEMM (512 threads, 4x4 warp grid) =================
// Out[128-row tile, 128 cols] = f( A1@W1^T [+ A2@W2^T] + b1 [+ b2] )
// bf16 3-pass split (hi*hi + hi*lo + lo*hi). Optional ELU, out_scale, fused BN stats.
#define A_HI 0
#define A_LO 32768
#define W_HI 65536
#define W_LO 98304
#define BN_OFF 131072
#define SMEM_TC (131072 + 1024 + 16)

__global__ __launch_bounds__(512, 1)
void gemm_tc(const float* __restrict__ A1, const __nv_bfloat16* __restrict__ W1p,
             const float* __restrict__ A2, const __nv_bfloat16* __restrict__ W2p,
             const float* __restrict__ bias1, const float* __restrict__ bias2,
             float out_scale, int do_elu, float* __restrict__ bn,
             float* __restrict__ Out, int M) {
    extern __shared__ char smem[];
    const uint32_t sb = s2u(smem);
    float* bnS = (float*)(smem + BN_OFF);

    const int tid = threadIdx.x;
    const int w = tid >> 5, lane = tid & 31;
    const int wm = w >> 2, wn = w & 3;          // 4 x 4 warp grid
    const int m_base = wm * 32, n_base = wn * 32;
    const int m0 = blockIdx.x * 128;
    const int qr = lane >> 2, qc = lane & 3;

    if (tid < 256) bnS[tid] = 0.f;

    float acc[2][4][4];
#pragma unroll
    for (int a = 0; a < 2; ++a)
#pragma unroll
        for (int b = 0; b < 4; ++b)
#pragma unroll
            for (int c = 0; c < 4; ++c) acc[a][b][c] = 0.f;

    const int P = (A2 != nullptr) ? 2 : 1;
    for (int p = 0; p < P; ++p) {
        const float* A = p ? A2 : A1;
        const __nv_bfloat16* Wp = p ? W2p : W1p;
        __syncthreads();
        // W hi+lo (64KB) via cp.async (pre-packed, linear)
        {
            const char* wg = (const char*)Wp;
#pragma unroll
            for (int it = 0; it < 8; ++it) {
                int i = tid + it * 512;
                cpasync16(sb + W_HI + i * 16, wg + (size_t)i * 16);
            }
            asm volatile("cp.async.commit_group;" ::: "memory");
        }
        // A tile [128x128] fp32 -> split hi/lo -> swizzled smem
#pragma unroll
        for (int it = 0; it < 4; ++it) {
            int idx = tid + it * 512;           // 2048 chunks of 8 floats
            int row = idx >> 4;
            int k0 = (idx & 15) << 3;
            int m = m0 + row;
            float4 a0 = make_float4(0.f, 0.f, 0.f, 0.f), a1 = a0;
            if (m < M) {
                const float* ap = A + (size_t)m * D + k0;
                a0 = *(const float4*)ap;
                a1 = *(const float4*)(ap + 4);
            }
            float av[8] = {a0.x, a0.y, a0.z, a0.w, a1.x, a1.y, a1.z, a1.w};
            __nv_bfloat16 hv[8], lv[8];
#pragma unroll
            for (int j = 0; j < 8; ++j) {
                hv[j] = __float2bfloat16(av[j]);
                lv[j] = __float2bfloat16(av[j] - __bfloat162float(hv[j]));
            }
            uint32_t off = sw_off(row, k0);
            *(uint4*)(smem + A_HI + off) = *(uint4*)hv;
            *(uint4*)(smem + A_LO + off) = *(uint4*)lv;
        }
        asm volatile("cp.async.wait_group 0;" ::: "memory");
        __syncthreads();

        for (int ks = 0; ks < 8; ++ks) {
            const int kc = ks * 16;
            uint32_t ah[2][4], al[2][4], bh[2][4], bl[2][4];
#pragma unroll
            for (int mt = 0; mt < 2; ++mt) {
                int row = m_base + mt * 16 + (lane & 15);
                int kk = kc + ((lane >> 4) << 3);
                uint32_t off = sw_off(row, kk);
                ldsm4(ah[mt][0], ah[mt][1], ah[mt][2], ah[mt][3], sb + A_HI + off);
                ldsm4(al[mt][0], al[mt][1], al[mt][2], al[mt][3], sb + A_LO + off);
            }
#pragma unroll
            for (int ng = 0; ng < 2; ++ng) {
                int n = n_base + ng * 16 + (lane & 7) + ((lane >> 4) << 3);
                int kk = kc + (((lane >> 3) & 1) << 3);
                uint32_t off = sw_off(n, kk);
                ldsm4(bh[ng][0], bh[ng][1], bh[ng][2], bh[ng][3], sb + W_HI + off);
                ldsm4(bl[ng][0], bl[ng][1], bl[ng][2], bl[ng][3], sb + W_LO + off);
            }
#pragma unroll
            for (int mt = 0; mt < 2; ++mt)
#pragma unroll
                for (int ng = 0; ng < 2; ++ng) {
                    mma16816(acc[mt][ng * 2 + 0], ah[mt][0], ah[mt][1], ah[mt][2], ah[mt][3],
                             bh[ng][0], bh[ng][1]);
                    mma16816(acc[mt][ng * 2 + 1], ah[mt][0], ah[mt][1], ah[mt][2], ah[mt][3],
                             bh[ng][2], bh[ng][3]);
                    mma16816(acc[mt][ng * 2 + 0], ah[mt][0], ah[mt][1], ah[mt][2], ah[mt][3],
                             bl[ng][0], bl[ng][1]);
                    mma16816(acc[mt][ng * 2 + 1], ah[mt][0], ah[mt][1], ah[mt][2], ah[mt][3],
                             bl[ng][2], bl[ng][3]);
                    mma16816(acc[mt][ng * 2 + 0], al[mt][0], al[mt][1], al[mt][2], al[mt][3],
                             bh[ng][0], bh[ng][1]);
                    mma16816(acc[mt][ng * 2 + 1], al[mt][0], al[mt][1], al[mt][2], al[mt][3],
                             bh[ng][2], bh[ng][3]);
                }
        }
    }

    // ---------------- epilogue ----------------
    float bcol[8];
#pragma unroll
    for (int nt = 0; nt < 4; ++nt)
#pragma unroll
        for (int par = 0; par < 2; ++par) {
            int c = n_base + nt * 8 + qc * 2 + par;
            float bb = 0.f;
            if (bias1 != nullptr) bb += bias1[c];
            if (bias2 != nullptr) bb += bias2[c];
            bcol[nt * 2 + par] = bb;
        }

    float cs[8], cq[8];
#pragma unroll
    for (int j = 0; j < 8; ++j) { cs[j] = 0.f; cq[j] = 0.f; }

#pragma unroll
    for (int mt = 0; mt < 2; ++mt)
#pragma unroll
        for (int jh = 0; jh < 2; ++jh) {
            int m = m0 + m_base + mt * 16 + qr + jh * 8;
            bool valid = (m < M);
            float2 vals[4];
#pragma unroll
            for (int nt = 0; nt < 4; ++nt) {
                float v0 = acc[mt][nt][jh * 2 + 0] + bcol[nt * 2 + 0];
                float v1 = acc[mt][nt][jh * 2 + 1] + bcol[nt * 2 + 1];
                if (do_elu) {
                    v0 = (v0 > 0.f) ? v0 : expm1f(v0);
                    v1 = (v1 > 0.f) ? v1 : expm1f(v1);
                }
                v0 *= out_scale; v1 *= out_scale;
                vals[nt] = make_float2(v0, v1);
                if (valid) {
                    cs[nt * 2 + 0] += v0; cq[nt * 2 + 0] += v0 * v0;
                    cs[nt * 2 + 1] += v1; cq[nt * 2 + 1] += v1 * v1;
                }
            }
            if (valid) {
                float* op = Out + (size_t)m * D + n_base + qc * 2;
#pragma unroll
                for (int nt = 0; nt < 4; ++nt)
                    *(float2*)(op + nt * 8) = vals[nt];
            }
        }

    if (bn != nullptr) {
#pragma unroll
        for (int j = 0; j < 8; ++j) {
#pragma unroll
            for (int o = 16; o >= 4; o >>= 1) {
                cs[j] += __shfl_down_sync(0xFFFFFFFFu, cs[j], o);
                cq[j] += __shfl_down_sync(0xFFFFFFFFu, cq[j], o);
            }
        }
        if (lane < 4) {
#pragma unroll
            for (int nt = 0; nt < 4; ++nt)
#pragma unroll
                for (int par = 0; par < 2; ++par) {
                    int c = n_base + nt * 8 + lane * 2 + par;
                    atomicAdd(&bnS[c], cs[nt * 2 + par]);
                    atomicAdd(&bnS[128 + c], cq[nt * 2 + par]);
                }
        }
        __syncthreads();
        if (tid < 256) atomicAdd(&bn[tid], bnS[tid]);
    }
}

// ================= batchnorm =================
__global__ void bn_final(const float* __restrict__ bn, const float* __restrict__ g,
                         const float* __restrict__ b, float* __restrict__ scale,
                         float* __restrict__ shift, float invN) {
    int c = threadIdx.x;
    float m = bn[c] * invN;
    float var = bn[D + c] * invN - m * m;
    float rs = rsqrtf(var + 1e-5f);
    float sc = g[c] * rs;
    scale[c] = sc;
    shift[c] = b[c] - m * sc;
}

__global__ void bn_apply(const float4* __restrict__ x, const float* __restrict__ scale,
                         const float* __restrict__ shift, float4* __restrict__ y, int n4) {
    int i = blockIdx.x * blockDim.x + threadIdx.x;
    if (i >= n4) return;
    int c = (i & 31) * 4;
    float4 v = x[i];
    v.x = v.x * scale[c + 0] + shift[c + 0];
    v.y = v.y * scale[c + 1] + shift[c + 1];
    v.z = v.z * scale[c + 2] + shift[c + 2];
    v.w = v.w * scale[c + 3] + shift[c + 3];
    y[i] = v;
}

// ================= host =================
static inline void launch_gemm(const float* A1, const __nv_bfloat16* W1p,
                               const float* A2, const __nv_bfloat16* W2p,
                               const float* b1, const float* b2,
                               float out_scale, int do_elu, float* bn,
                               float* Out, int M) {
    gemm_tc<<<(M + 127) / 128, 512, SMEM_TC>>>(A1, W1p, A2, W2p, b1, b2,
                                               out_scale, do_elu, bn, Out, M);
}

static inline void build_csr(const int* src, const int* dst, int E, int N,
                             int* deg, int* bsum, int* rp, int* col) {
    int M = N + 1;
    int nb = (M + 1023) / 1024;
    zero_int<<<(M + 255) / 256, 256>>>(deg, M);
    hist_kernel<<<(E + 255) / 256, 256>>>(dst, E, deg);
    scan_sum<<<nb, 256>>>(deg, bsum, M);
    scan_offsets<<<1, 32>>>(bsum, nb);
    scan_block<<<nb, 256>>>(deg, bsum, rp, M);
    zero_int<<<(N + 255) / 256, 256>>>(deg, N);
    fill_kernel<<<(E + 255) / 256, 256>>>(src, dst, E, rp, deg, col);
}

extern "C" void kernel_launch(void* const* d_in, const int* in_sizes, int n_in,
                              void* d_out, int out_size) {
    const float* x_student = (const float*)d_in[0];
    const float* x_item    = (const float*)d_in[1];
    const float* Wl_ri = (const float*)d_in[2];
    const float* bl_ri = (const float*)d_in[3];
    const float* Wr_ri = (const float*)d_in[4];
    const float* Wl_rs = (const float*)d_in[5];
    const float* bl_rs = (const float*)d_in[6];
    const float* Wr_rs = (const float*)d_in[7];
    const float* W_p   = (const float*)d_in[8];
    const float* b_p   = (const float*)d_in[9];
    const float* bn_g  = (const float*)d_in[10];
    const float* bn_b  = (const float*)d_in[11];
    const int* resp_src = (const int*)d_in[12];
    const int* resp_dst = (const int*)d_in[13];
    const int* rev_src  = (const int*)d_in[14];
    const int* rev_dst  = (const int*)d_in[15];
    const int* prec_src = (const int*)d_in[16];
    const int* prec_dst = (const int*)d_in[17];
    float* out = (float*)d_out;

    static int configured = 0;
    if (!configured) {
        cudaFuncSetAttribute(gemm_tc, cudaFuncAttributeMaxDynamicSharedMemorySize, SMEM_TC);
        configured = 1;
    }

    float *agg_s, *agg_i, *h, *xs, *xi, *item, *bn, *bnscale, *bnshift;
    __nv_bfloat16* wpack;
    int *deg, *bsum, *rp_resp, *rp_rev, *rp_prec, *col_resp, *col_rev, *col_prec;
    cudaGetSymbolAddress((void**)&agg_s,  g_agg_s);
    cudaGetSymbolAddress((void**)&agg_i,  g_agg_i);
    cudaGetSymbolAddress((void**)&h,      g_h);
    cudaGetSymbolAddress((void**)&xs,     g_xs);
    cudaGetSymbolAddress((void**)&xi,     g_xi);
    cudaGetSymbolAddress((void**)&item,   g_item);
    cudaGetSymbolAddress((void**)&bn,     g_bn);
    cudaGetSymbolAddress((void**)&bnscale, g_bnscale);
    cudaGetSymbolAddress((void**)&bnshift, g_bnshift);
    cudaGetSymbolAddress((void**)&wpack,  g_wpack);
    cudaGetSymbolAddress((void**)&deg,     g_deg);
    cudaGetSymbolAddress((void**)&bsum,    g_bsum);
    cudaGetSymbolAddress((void**)&rp_resp, g_rp_resp);
    cudaGetSymbolAddress((void**)&rp_rev,  g_rp_rev);
    cudaGetSymbolAddress((void**)&rp_prec, g_rp_prec);
    cudaGetSymbolAddress((void**)&col_resp, g_col_resp);
    cudaGetSymbolAddress((void**)&col_rev,  g_col_rev);
    cudaGetSymbolAddress((void**)&col_prec, g_col_prec);

    // pre-split all weights to bf16 hi/lo swizzled images
    pack_w<<<(10 * 16384 + 255) / 256, 256>>>(Wl_ri, Wr_ri, Wl_rs, Wr_rs, W_p, wpack);

    // build CSR for the 3 edge lists (layer-invariant)
    build_csr(resp_src, resp_dst, E1, NI, deg, bsum, rp_resp, col_resp);
    build_csr(rev_src,  rev_dst,  E1, NS, deg, bsum, rp_rev,  col_rev);
    build_csr(prec_src, prec_dst, E2, NS, deg, bsum, rp_prec, col_prec);

    for (int l = 0; l < L; ++l) {
        const float* xs_in = l ? (const float*)xs : x_student;
        const float* xi_in = l ? (const float*)xi : x_item;
        float* xi_out = (l == L - 1) ? out : xi;
        float* xs_out = (l == L - 1) ? out + (size_t)NI * D : xs;
        const __nv_bfloat16* wp0 = wpack + (size_t)(l * 5 + 0) * 32768;  // Wl_ri
        const __nv_bfloat16* wp1 = wpack + (size_t)(l * 5 + 1) * 32768;  // Wr_ri
        const __nv_bfloat16* wp2 = wpack + (size_t)(l * 5 + 2) * 32768;  // Wl_rs
        const __nv_bfloat16* wp3 = wpack + (size_t)(l * 5 + 3) * 32768;  // Wr_rs
        const __nv_bfloat16* wp4 = wpack + (size_t)(l * 5 + 4) * 32768;  // W_p

        // mean aggregations (division fused; no zero fill needed)
        agg_csr<<<(NI * 32 + 255) / 256, 256>>>(xs_in, rp_resp, col_resp, NI, 0, 0.f, agg_i);
        agg_csr<<<(NS * 32 + 255) / 256, 256>>>(xi_in, rp_rev,  col_rev,  NS, 0, 0.f, agg_s);
        zero_kernel<<<1, 64>>>((float4*)bn, 2 * D / 4);

        // item = elu(agg_i @ Wl_ri^T + bl_ri + xi @ Wr_ri^T); BN stats fused
        launch_gemm(agg_i, wp0, xi_in, wp1,
                    bl_ri + (size_t)l * D, nullptr, 1.f, 1, bn, item, NI);

        // h = xs @ W_p^T
        launch_gemm(xs_in, wp4, nullptr, nullptr,
                    nullptr, nullptr, 1.f, 0, nullptr, h, NS);

        // stu = 0.5*(agg_s @ Wl_rs^T + bl_rs + xs @ Wr_rs^T + b_p)
        launch_gemm(agg_s, wp2, xs_in, wp3,
                    bl_rs + (size_t)l * D, b_p + (size_t)l * D, 0.5f, 0, nullptr, xs_out, NS);

        // stu += 0.5 * sum(h[src] -> dst)
        agg_csr<<<(NS * 32 + 255) / 256, 256>>>(h, rp_prec, col_prec, NS, 1, 0.5f, xs_out);

        // batchnorm on item -> xi_out
        bn_final<<<1, 128>>>(bn, bn_g + (size_t)l * D, bn_b + (size_t)l * D,
                             bnscale, bnshift, 1.f / (float)NI);
        bn_apply<<<(NI * 32 + 255) / 256, 256>>>((const float4*)item, bnscale, bnshift,
                                                 (float4*)xi_out, NI * 32);
    }
}

// round 6
// speedup vs baseline: 1.2296x; 1.2296x over previous
#include <cuda_runtime.h>
#include <cuda_bf16.h>
#include <math.h>
#include <stdint.h>

#define NS 100000
#define NI 20000
#define D  128
#define L  2
#define E1 600000
#define E2 500000

// ---------------- scratch (static device globals: allocation-free) ----------------
__device__ float g_agg_s[(size_t)NS * D];
__device__ float g_agg_i[(size_t)NI * D];
__device__ float g_h   [(size_t)NS * D];
__device__ float g_xs  [(size_t)NS * D];
__device__ float g_xi  [(size_t)NI * D];
__device__ float g_item[(size_t)NI * D];
__device__ float g_bn[2 * D];
__device__ float g_bnscale[D];
__device__ float g_bnshift[D];
// packed weights: 10 matrices (2 layers x 5): hi image (16384 bf16) + lo image (16384 bf16)
__device__ __nv_bfloat16 g_wpack[10 * 32768];
// CSR structures (private scratch per edge list so builds can run concurrently)
__device__ int g_deg_a[NI + 2];
__device__ int g_deg_b[NS + 2];
__device__ int g_deg_c[NS + 2];
__device__ int g_bsum_a[128];
__device__ int g_bsum_b[128];
__device__ int g_bsum_c[128];
__device__ int g_rp_resp[NI + 1];
__device__ int g_rp_rev[NS + 1];
__device__ int g_rp_prec[NS + 1];
__device__ int g_col_resp[E1];
__device__ int g_col_rev[E1];
__device__ int g_col_prec[E2];

// ---------------- smem swizzle: 128 rows x 256B, 16B chunks XOR'd by row ----------------
__device__ __forceinline__ uint32_t sw_off(int row, int k) {
    return (uint32_t)(row * 256 + (((k >> 3) ^ (row & 7)) << 4) + ((k & 7) << 1));
}

__device__ __forceinline__ uint32_t s2u(const void* p) {
    uint32_t a;
    asm("{ .reg .u64 t; cvta.to.shared.u64 t, %1; cvt.u32.u64 %0, t; }" : "=r"(a) : "l"(p));
    return a;
}

__device__ __forceinline__ void ldsm4(uint32_t& r0, uint32_t& r1, uint32_t& r2, uint32_t& r3,
                                      uint32_t addr) {
    asm volatile("ldmatrix.sync.aligned.m8n8.x4.shared.b16 {%0,%1,%2,%3}, [%4];"
                 : "=r"(r0), "=r"(r1), "=r"(r2), "=r"(r3) : "r"(addr));
}

__device__ __forceinline__ void mma16816(float* c, uint32_t a0, uint32_t a1, uint32_t a2,
                                         uint32_t a3, uint32_t b0, uint32_t b1) {
    asm volatile("mma.sync.aligned.m16n8k16.row.col.f32.bf16.bf16.f32 "
                 "{%0,%1,%2,%3}, {%4,%5,%6,%7}, {%8,%9}, {%0,%1,%2,%3};"
                 : "+f"(c[0]), "+f"(c[1]), "+f"(c[2]), "+f"(c[3])
                 : "r"(a0), "r"(a1), "r"(a2), "r"(a3), "r"(b0), "r"(b1));
}

__device__ __forceinline__ void cpasync16(uint32_t s, const void* g) {
    asm volatile("cp.async.cg.shared.global [%0], [%1], 16;" :: "r"(s), "l"(g));
}

// ================= utility kernels =================
__global__ void zero_kernel(float4* __restrict__ p, int n4) {
    int i = blockIdx.x * blockDim.x + threadIdx.x;
    if (i < n4) p[i] = make_float4(0.f, 0.f, 0.f, 0.f);
}
__global__ void zero_int(int* __restrict__ p, int n) {
    int i = blockIdx.x * blockDim.x + threadIdx.x;
    if (i < n) p[i] = 0;
}

// ================= CSR build =================
__global__ void hist_kernel(const int* __restrict__ dst, int E, int* __restrict__ deg) {
    int e = blockIdx.x * blockDim.x + threadIdx.x;
    if (e < E) atomicAdd(&deg[dst[e]], 1);
}

__global__ void scan_sum(const int* __restrict__ deg, int* __restrict__ bsum, int M) {
    __shared__ int wsum[8];
    int t = threadIdx.x;
    int base = blockIdx.x * 1024 + t * 4;
    int s = 0;
#pragma unroll
    for (int j = 0; j < 4; ++j) s += (base + j < M) ? deg[base + j] : 0;
#pragma unroll
    for (int o = 16; o > 0; o >>= 1) s += __shfl_down_sync(0xFFFFFFFFu, s, o);
    if ((t & 31) == 0) wsum[t >> 5] = s;
    __syncthreads();
    if (t == 0) {
        int r = 0;
#pragma unroll
        for (int w = 0; w < 8; ++w) r += wsum[w];
        bsum[blockIdx.x] = r;
    }
}

__global__ void scan_offsets(int* __restrict__ bsum, int nb) {
    if (threadIdx.x == 0 && blockIdx.x == 0) {
        int r = 0;
        for (int b = 0; b < nb; ++b) { int x = bsum[b]; bsum[b] = r; r += x; }
    }
}

__global__ void scan_block(const int* __restrict__ deg, const int* __restrict__ bsum,
                           int* __restrict__ rp, int M) {
    __shared__ int wsum[8];
    int t = threadIdx.x, lane = t & 31, wid = t >> 5;
    int base = blockIdx.x * 1024 + t * 4;
    int v[4];
#pragma unroll
    for (int j = 0; j < 4; ++j) v[j] = (base + j < M) ? deg[base + j] : 0;
    int tsum = v[0] + v[1] + v[2] + v[3];
    int incl = tsum;
#pragma unroll
    for (int o = 1; o < 32; o <<= 1) {
        int n = __shfl_up_sync(0xFFFFFFFFu, incl, o);
        if (lane >= o) incl += n;
    }
    if (lane == 31) wsum[wid] = incl;
    __syncthreads();
    if (t == 0) {
        int r = 0;
#pragma unroll
        for (int w = 0; w < 8; ++w) { int x = wsum[w]; wsum[w] = r; r += x; }
    }
    __syncthreads();
    int run = incl - tsum + wsum[wid] + bsum[blockIdx.x];
#pragma unroll
    for (int j = 0; j < 4; ++j) {
        if (base + j < M) { rp[base + j] = run; run += v[j]; }
    }
}

__global__ void fill_kernel(const int* __restrict__ src, const int* __restrict__ dst, int E,
                            const int* __restrict__ rp, int* __restrict__ fillc,
                            int* __restrict__ col) {
    int e = blockIdx.x * blockDim.x + threadIdx.x;
    if (e >= E) return;
    int d = dst[e];
    int pos = rp[d] + atomicAdd(&fillc[d], 1);
    col[pos] = src[e];
}

// ================= CSR aggregation: warp per destination row =================
// mode 0: out[r] = (1/max(deg,1)) * sum_{i} X[col[i]]
// mode 1: out[r] += coef * sum_{i} X[col[i]]
__global__ void agg_csr(const float* __restrict__ X, const int* __restrict__ rp,
                        const int* __restrict__ col, int N, int mode, float coef,
                        float* __restrict__ out) {
    int r = (int)((blockIdx.x * (unsigned)blockDim.x + threadIdx.x) >> 5);
    int lane = threadIdx.x & 31;
    if (r >= N) return;
    int beg = rp[r], end = rp[r + 1];
    float4 acc = make_float4(0.f, 0.f, 0.f, 0.f);
    int i = beg;
    int s_next = (i < end) ? __ldg(col + i) : 0;
    while (i < end) {
        int s = s_next;
        ++i;
        s_next = (i < end) ? __ldg(col + i) : 0;
        float4 v = __ldg((const float4*)(X + (size_t)s * D + lane * 4));
        acc.x += v.x; acc.y += v.y; acc.z += v.z; acc.w += v.w;
    }
    float sc = (mode == 0) ? (1.f / fmaxf((float)(end - beg), 1.f)) : coef;
    acc.x *= sc; acc.y *= sc; acc.z *= sc; acc.w *= sc;
    float* op = out + (size_t)r * D + lane * 4;
    if (mode == 1) {
        float4 o = *(const float4*)op;
        acc.x += o.x; acc.y += o.y; acc.z += o.z; acc.w += o.w;
    }
    *(float4*)op = acc;
}

// Pack all 10 weight matrices into bf16 hi/lo swizzled images ([n][k] rows of 256B).
__global__ void pack_w(const float* __restrict__ Wl_ri, const float* __restrict__ Wr_ri,
                       const float* __restrict__ Wl_rs, const float* __restrict__ Wr_rs,
                       const float* __restrict__ W_p, __nv_bfloat16* __restrict__ dst) {
    int gid = blockIdx.x * blockDim.x + threadIdx.x;
    if (gid >= 10 * 16384) return;
    int mid = gid >> 14;
    int idx = gid & 16383;
    int l = mid / 5, which = mid % 5;
    const float* src;
    switch (which) {
        case 0: src = Wl_ri; break;
        case 1: src = Wr_ri; break;
        case 2: src = Wl_rs; break;
        case 3: src = Wr_rs; break;
        default: src = W_p; break;
    }
    float a = src[(size_t)l * 16384 + idx];
    int n = idx >> 7, k = idx & 127;
    __nv_bfloat16 hi = __float2bfloat16(a);
    __nv_bfloat16 lo = __float2bfloat16(a - __bfloat162float(hi));
    uint32_t off = sw_off(n, k) >> 1;
    dst[(size_t)mid * 32768 + off] = hi;
    dst[(size_t)mid * 32768 + 16384 + off] = lo;
}

// ================= HMMA fused GEMM (512 threads, 4x4 warp grid) =================
#define A_HI 0
#define A_LO 32768
#define W_HI 65536
#define W_LO 98304
#define BN_OFF 131072
#define SMEM_TC (131072 + 1024 + 16)

__global__ __launch_bounds__(512, 1)
void gemm_tc(const float* __restrict__ A1, const __nv_bfloat16* __restrict__ W1p,
             const float* __restrict__ A2, const __nv_bfloat16* __restrict__ W2p,
             const float* __restrict__ bias1, const float* __restrict__ bias2,
             float out_scale, int do_elu, float* __restrict__ bn,
             float* __restrict__ Out, int M) {
    extern __shared__ char smem[];
    const uint32_t sb = s2u(smem);
    float* bnS = (float*)(smem + BN_OFF);

    const int tid = threadIdx.x;
    const int w = tid >> 5, lane = tid & 31;
    const int wm = w >> 2, wn = w & 3;          // 4 x 4 warp grid
    const int m_base = wm * 32, n_base = wn * 32;
    const int m0 = blockIdx.x * 128;
    const int qr = lane >> 2, qc = lane & 3;

    if (tid < 256) bnS[tid] = 0.f;

    float acc[2][4][4];
#pragma unroll
    for (int a = 0; a < 2; ++a)
#pragma unroll
        for (int b = 0; b < 4; ++b)
#pragma unroll
            for (int c = 0; c < 4; ++c) acc[a][b][c] = 0.f;

    const int P = (A2 != nullptr) ? 2 : 1;
    for (int p = 0; p < P; ++p) {
        const float* A = p ? A2 : A1;
        const __nv_bfloat16* Wp = p ? W2p : W1p;
        __syncthreads();
        // W hi+lo (64KB) via cp.async (pre-packed, linear)
        {
            const char* wg = (const char*)Wp;
#pragma unroll
            for (int it = 0; it < 8; ++it) {
                int i = tid + it * 512;
                cpasync16(sb + W_HI + i * 16, wg + (size_t)i * 16);
            }
            asm volatile("cp.async.commit_group;" ::: "memory");
        }
        // A tile [128x128] fp32 -> split hi/lo -> swizzled smem
#pragma unroll
        for (int it = 0; it < 4; ++it) {
            int idx = tid + it * 512;
            int row = idx >> 4;
            int k0 = (idx & 15) << 3;
            int m = m0 + row;
            float4 a0 = make_float4(0.f, 0.f, 0.f, 0.f), a1 = a0;
            if (m < M) {
                const float* ap = A + (size_t)m * D + k0;
                a0 = *(const float4*)ap;
                a1 = *(const float4*)(ap + 4);
            }
            float av[8] = {a0.x, a0.y, a0.z, a0.w, a1.x, a1.y, a1.z, a1.w};
            __nv_bfloat16 hv[8], lv[8];
#pragma unroll
            for (int j = 0; j < 8; ++j) {
                hv[j] = __float2bfloat16(av[j]);
                lv[j] = __float2bfloat16(av[j] - __bfloat162float(hv[j]));
            }
            uint32_t off = sw_off(row, k0);
            *(uint4*)(smem + A_HI + off) = *(uint4*)hv;
            *(uint4*)(smem + A_LO + off) = *(uint4*)lv;
        }
        asm volatile("cp.async.wait_group 0;" ::: "memory");
        __syncthreads();

        for (int ks = 0; ks < 8; ++ks) {
            const int kc = ks * 16;
            uint32_t ah[2][4], al[2][4], bh[2][4], bl[2][4];
#pragma unroll
            for (int mt = 0; mt < 2; ++mt) {
                int row = m_base + mt * 16 + (lane & 15);
                int kk = kc + ((lane >> 4) << 3);
                uint32_t off = sw_off(row, kk);
                ldsm4(ah[mt][0], ah[mt][1], ah[mt][2], ah[mt][3], sb + A_HI + off);
                ldsm4(al[mt][0], al[mt][1], al[mt][2], al[mt][3], sb + A_LO + off);
            }
#pragma unroll
            for (int ng = 0; ng < 2; ++ng) {
                int n = n_base + ng * 16 + (lane & 7) + ((lane >> 4) << 3);
                int kk = kc + (((lane >> 3) & 1) << 3);
                uint32_t off = sw_off(n, kk);
                ldsm4(bh[ng][0], bh[ng][1], bh[ng][2], bh[ng][3], sb + W_HI + off);
                ldsm4(bl[ng][0], bl[ng][1], bl[ng][2], bl[ng][3], sb + W_LO + off);
            }
#pragma unroll
            for (int mt = 0; mt < 2; ++mt)
#pragma unroll
                for (int ng = 0; ng < 2; ++ng) {
                    mma16816(acc[mt][ng * 2 + 0], ah[mt][0], ah[mt][1], ah[mt][2], ah[mt][3],
                             bh[ng][0], bh[ng][1]);
                    mma16816(acc[mt][ng * 2 + 1], ah[mt][0], ah[mt][1], ah[mt][2], ah[mt][3],
                             bh[ng][2], bh[ng][3]);
                    mma16816(acc[mt][ng * 2 + 0], ah[mt][0], ah[mt][1], ah[mt][2], ah[mt][3],
                             bl[ng][0], bl[ng][1]);
                    mma16816(acc[mt][ng * 2 + 1], ah[mt][0], ah[mt][1], ah[mt][2], ah[mt][3],
                             bl[ng][2], bl[ng][3]);
                    mma16816(acc[mt][ng * 2 + 0], al[mt][0], al[mt][1], al[mt][2], al[mt][3],
                             bh[ng][0], bh[ng][1]);
                    mma16816(acc[mt][ng * 2 + 1], al[mt][0], al[mt][1], al[mt][2], al[mt][3],
                             bh[ng][2], bh[ng][3]);
                }
        }
    }

    // ---------------- epilogue ----------------
    float bcol[8];
#pragma unroll
    for (int nt = 0; nt < 4; ++nt)
#pragma unroll
        for (int par = 0; par < 2; ++par) {
            int c = n_base + nt * 8 + qc * 2 + par;
            float bb = 0.f;
            if (bias1 != nullptr) bb += bias1[c];
            if (bias2 != nullptr) bb += bias2[c];
            bcol[nt * 2 + par] = bb;
        }

    float cs[8], cq[8];
#pragma unroll
    for (int j = 0; j < 8; ++j) { cs[j] = 0.f; cq[j] = 0.f; }

#pragma unroll
    for (int mt = 0; mt < 2; ++mt)
#pragma unroll
        for (int jh = 0; jh < 2; ++jh) {
            int m = m0 + m_base + mt * 16 + qr + jh * 8;
            bool valid = (m < M);
            float2 vals[4];
#pragma unroll
            for (int nt = 0; nt < 4; ++nt) {
                float v0 = acc[mt][nt][jh * 2 + 0] + bcol[nt * 2 + 0];
                float v1 = acc[mt][nt][jh * 2 + 1] + bcol[nt * 2 + 1];
                if (do_elu) {
                    v0 = (v0 > 0.f) ? v0 : expm1f(v0);
                    v1 = (v1 > 0.f) ? v1 : expm1f(v1);
                }
                v0 *= out_scale; v1 *= out_scale;
                vals[nt] = make_float2(v0, v1);
                if (valid) {
                    cs[nt * 2 + 0] += v0; cq[nt * 2 + 0] += v0 * v0;
                    cs[nt * 2 + 1] += v1; cq[nt * 2 + 1] += v1 * v1;
                }
            }
            if (valid) {
                float* op = Out + (size_t)m * D + n_base + qc * 2;
#pragma unroll
                for (int nt = 0; nt < 4; ++nt)
                    *(float2*)(op + nt * 8) = vals[nt];
            }
        }

    if (bn != nullptr) {
#pragma unroll
        for (int j = 0; j < 8; ++j) {
#pragma unroll
            for (int o = 16; o >= 4; o >>= 1) {
                cs[j] += __shfl_down_sync(0xFFFFFFFFu, cs[j], o);
                cq[j] += __shfl_down_sync(0xFFFFFFFFu, cq[j], o);
            }
        }
        if (lane < 4) {
#pragma unroll
            for (int nt = 0; nt < 4; ++nt)
#pragma unroll
                for (int par = 0; par < 2; ++par) {
                    int c = n_base + nt * 8 + lane * 2 + par;
                    atomicAdd(&bnS[c], cs[nt * 2 + par]);
                    atomicAdd(&bnS[128 + c], cq[nt * 2 + par]);
                }
        }
        __syncthreads();
        if (tid < 256) atomicAdd(&bn[tid], bnS[tid]);
    }
}

// ================= batchnorm =================
__global__ void bn_final(const float* __restrict__ bn, const float* __restrict__ g,
                         const float* __restrict__ b, float* __restrict__ scale,
                         float* __restrict__ shift, float invN) {
    int c = threadIdx.x;
    float m = bn[c] * invN;
    float var = bn[D + c] * invN - m * m;
    float rs = rsqrtf(var + 1e-5f);
    float sc = g[c] * rs;
    scale[c] = sc;
    shift[c] = b[c] - m * sc;
}

__global__ void bn_apply(const float4* __restrict__ x, const float* __restrict__ scale,
                         const float* __restrict__ shift, float4* __restrict__ y, int n4) {
    int i = blockIdx.x * blockDim.x + threadIdx.x;
    if (i >= n4) return;
    int c = (i & 31) * 4;
    float4 v = x[i];
    v.x = v.x * scale[c + 0] + shift[c + 0];
    v.y = v.y * scale[c + 1] + shift[c + 1];
    v.z = v.z * scale[c + 2] + shift[c + 2];
    v.w = v.w * scale[c + 3] + shift[c + 3];
    y[i] = v;
}

// ================= host =================
static inline void launch_gemm(const float* A1, const __nv_bfloat16* W1p,
                               const float* A2, const __nv_bfloat16* W2p,
                               const float* b1, const float* b2,
                               float out_scale, int do_elu, float* bn,
                               float* Out, int M, cudaStream_t st) {
    gemm_tc<<<(M + 127) / 128, 512, SMEM_TC, st>>>(A1, W1p, A2, W2p, b1, b2,
                                                   out_scale, do_elu, bn, Out, M);
}

static inline void build_csr(const int* src, const int* dst, int E, int N,
                             int* deg, int* bsum, int* rp, int* col, cudaStream_t st) {
    int M = N + 1;
    int nb = (M + 1023) / 1024;
    zero_int<<<(M + 255) / 256, 256, 0, st>>>(deg, M);
    hist_kernel<<<(E + 255) / 256, 256, 0, st>>>(dst, E, deg);
    scan_sum<<<nb, 256, 0, st>>>(deg, bsum, M);
    scan_offsets<<<1, 32, 0, st>>>(bsum, nb);
    scan_block<<<nb, 256, 0, st>>>(deg, bsum, rp, M);
    zero_int<<<(N + 255) / 256, 256, 0, st>>>(deg, N);
    fill_kernel<<<(E + 255) / 256, 256, 0, st>>>(src, dst, E, rp, deg, col);
}

extern "C" void kernel_launch(void* const* d_in, const int* in_sizes, int n_in,
                              void* d_out, int out_size) {
    const float* x_student = (const float*)d_in[0];
    const float* x_item    = (const float*)d_in[1];
    const float* Wl_ri = (const float*)d_in[2];
    const float* bl_ri = (const float*)d_in[3];
    const float* Wr_ri = (const float*)d_in[4];
    const float* Wl_rs = (const float*)d_in[5];
    const float* bl_rs = (const float*)d_in[6];
    const float* Wr_rs = (const float*)d_in[7];
    const float* W_p   = (const float*)d_in[8];
    const float* b_p   = (const float*)d_in[9];
    const float* bn_g  = (const float*)d_in[10];
    const float* bn_b  = (const float*)d_in[11];
    const int* resp_src = (const int*)d_in[12];
    const int* resp_dst = (const int*)d_in[13];
    const int* rev_src  = (const int*)d_in[14];
    const int* rev_dst  = (const int*)d_in[15];
    const int* prec_src = (const int*)d_in[16];
    const int* prec_dst = (const int*)d_in[17];
    float* out = (float*)d_out;

    static int configured = 0;
    static cudaStream_t s1, s2, s3;
    static cudaEvent_t evRoot, evPack, evRev, evB3, evH1, evH2, evXs1, evXi1, evDone1;
    if (!configured) {
        cudaFuncSetAttribute(gemm_tc, cudaFuncAttributeMaxDynamicSharedMemorySize, SMEM_TC);
        cudaStreamCreateWithFlags(&s1, cudaStreamNonBlocking);
        cudaStreamCreateWithFlags(&s2, cudaStreamNonBlocking);
        cudaStreamCreateWithFlags(&s3, cudaStreamNonBlocking);
        cudaEventCreateWithFlags(&evRoot, cudaEventDisableTiming);
        cudaEventCreateWithFlags(&evPack, cudaEventDisableTiming);
        cudaEventCreateWithFlags(&evRev, cudaEventDisableTiming);
        cudaEventCreateWithFlags(&evB3, cudaEventDisableTiming);
        cudaEventCreateWithFlags(&evH1, cudaEventDisableTiming);
        cudaEventCreateWithFlags(&evH2, cudaEventDisableTiming);
        cudaEventCreateWithFlags(&evXs1, cudaEventDisableTiming);
        cudaEventCreateWithFlags(&evXi1, cudaEventDisableTiming);
        cudaEventCreateWithFlags(&evDone1, cudaEventDisableTiming);
        configured = 1;
    }

    float *agg_s, *agg_i, *h, *xs, *xi, *item, *bn, *bnscale, *bnshift;
    __nv_bfloat16* wpack;
    int *deg_a, *deg_b, *deg_c, *bsum_a, *bsum_b, *bsum_c;
    int *rp_resp, *rp_rev, *rp_prec, *col_resp, *col_rev, *col_prec;
    cudaGetSymbolAddress((void**)&agg_s,  g_agg_s);
    cudaGetSymbolAddress((void**)&agg_i,  g_agg_i);
    cudaGetSymbolAddress((void**)&h,      g_h);
    cudaGetSymbolAddress((void**)&xs,     g_xs);
    cudaGetSymbolAddress((void**)&xi,     g_xi);
    cudaGetSymbolAddress((void**)&item,   g_item);
    cudaGetSymbolAddress((void**)&bn,     g_bn);
    cudaGetSymbolAddress((void**)&bnscale, g_bnscale);
    cudaGetSymbolAddress((void**)&bnshift, g_bnshift);
    cudaGetSymbolAddress((void**)&wpack,  g_wpack);
    cudaGetSymbolAddress((void**)&deg_a,   g_deg_a);
    cudaGetSymbolAddress((void**)&deg_b,   g_deg_b);
    cudaGetSymbolAddress((void**)&deg_c,   g_deg_c);
    cudaGetSymbolAddress((void**)&bsum_a,  g_bsum_a);
    cudaGetSymbolAddress((void**)&bsum_b,  g_bsum_b);
    cudaGetSymbolAddress((void**)&bsum_c,  g_bsum_c);
    cudaGetSymbolAddress((void**)&rp_resp, g_rp_resp);
    cudaGetSymbolAddress((void**)&rp_rev,  g_rp_rev);
    cudaGetSymbolAddress((void**)&rp_prec, g_rp_prec);
    cudaGetSymbolAddress((void**)&col_resp, g_col_resp);
    cudaGetSymbolAddress((void**)&col_rev,  g_col_rev);
    cudaGetSymbolAddress((void**)&col_prec, g_col_prec);

    // ---------- fork ----------
    cudaEventRecord(evRoot, 0);
    cudaStreamWaitEvent(s1, evRoot, 0);
    cudaStreamWaitEvent(s2, evRoot, 0);
    cudaStreamWaitEvent(s3, evRoot, 0);

    // stream 0: weight packing; s1/s2/s3: the three CSR builds (private scratch)
    pack_w<<<(10 * 16384 + 255) / 256, 256>>>(Wl_ri, Wr_ri, Wl_rs, Wr_rs, W_p, wpack);
    cudaEventRecord(evPack, 0);
    build_csr(resp_src, resp_dst, E1, NI, deg_a, bsum_a, rp_resp, col_resp, s1);
    build_csr(rev_src,  rev_dst,  E1, NS, deg_b, bsum_b, rp_rev,  col_rev,  s2);
    cudaEventRecord(evRev, s2);
    build_csr(prec_src, prec_dst, E2, NS, deg_c, bsum_c, rp_prec, col_prec, s3);
    cudaEventRecord(evB3, s3);

    // s1 and s2 need packed weights for their GEMMs
    cudaStreamWaitEvent(s1, evPack, 0);
    cudaStreamWaitEvent(s2, evPack, 0);

    // =================== layer 1 ===================
    // s1: agg_i -> item-GEMM -> bn_final -> bn_apply -> xi   (resp build on s1, ordered)
    agg_csr<<<(NI * 32 + 255) / 256, 256, 0, s1>>>(x_student, rp_resp, col_resp, NI, 0, 0.f, agg_i);
    zero_kernel<<<1, 64, 0, s1>>>((float4*)bn, 2 * D / 4);
    launch_gemm(agg_i, wpack + (size_t)0 * 32768, x_item, wpack + (size_t)1 * 32768,
                bl_ri, nullptr, 1.f, 1, bn, item, NI, s1);
    bn_final<<<1, 128, 0, s1>>>(bn, bn_g, bn_b, bnscale, bnshift, 1.f / (float)NI);
    bn_apply<<<(NI * 32 + 255) / 256, 256, 0, s1>>>((const float4*)item, bnscale, bnshift,
                                                    (float4*)xi, NI * 32);
    cudaEventRecord(evXi1, s1);

    // s2: h = x_student @ W_p^T
    launch_gemm(x_student, wpack + (size_t)4 * 32768, nullptr, nullptr,
                nullptr, nullptr, 1.f, 0, nullptr, h, NS, s2);
    cudaEventRecord(evH1, s2);

    // stream 0 (critical path): agg_s -> stu-GEMM -> prec-agg -> xs
    cudaStreamWaitEvent(0, evRev, 0);
    agg_csr<<<(NS * 32 + 255) / 256, 256>>>(x_item, rp_rev, col_rev, NS, 0, 0.f, agg_s);
    launch_gemm(agg_s, wpack + (size_t)2 * 32768, x_student, wpack + (size_t)3 * 32768,
                bl_rs, b_p, 0.5f, 0, nullptr, xs, NS, 0);
    cudaStreamWaitEvent(0, evH1, 0);
    cudaStreamWaitEvent(0, evB3, 0);
    agg_csr<<<(NS * 32 + 255) / 256, 256>>>(h, rp_prec, col_prec, NS, 1, 0.5f, xs);
    cudaEventRecord(evXs1, 0);

    // =================== layer 2 ===================
    const size_t woff = 5 * 32768;
    float* xi_out = out;                       // items first in output
    float* xs_out = out + (size_t)NI * D;

    // s1: agg_i(xs) -> item-GEMM -> bn -> bn_apply -> out (items)
    cudaStreamWaitEvent(s1, evXs1, 0);
    agg_csr<<<(NI * 32 + 255) / 256, 256, 0, s1>>>(xs, rp_resp, col_resp, NI, 0, 0.f, agg_i);
    zero_kernel<<<1, 64, 0, s1>>>((float4*)bn, 2 * D / 4);
    launch_gemm(agg_i, wpack + woff + 0 * 32768, xi, wpack + woff + 1 * 32768,
                bl_ri + D, nullptr, 1.f, 1, bn, item, NI, s1);
    bn_final<<<1, 128, 0, s1>>>(bn, bn_g + D, bn_b + D, bnscale, bnshift, 1.f / (float)NI);
    bn_apply<<<(NI * 32 + 255) / 256, 256, 0, s1>>>((const float4*)item, bnscale, bnshift,
                                                    (float4*)xi_out, NI * 32);
    cudaEventRecord(evDone1, s1);

    // s2: h = xs @ W_p^T (layer 2)
    cudaStreamWaitEvent(s2, evXs1, 0);
    launch_gemm(xs, wpack + woff + 4 * 32768, nullptr, nullptr,
                nullptr, nullptr, 1.f, 0, nullptr, h, NS, s2);
    cudaEventRecord(evH2, s2);

    // stream 0: agg_s(xi) -> stu-GEMM -> prec-agg -> out (students)
    cudaStreamWaitEvent(0, evXi1, 0);
    agg_csr<<<(NS * 32 + 255) / 256, 256>>>(xi, rp_rev, col_rev, NS, 0, 0.f, agg_s);
    launch_gemm(agg_s, wpack + woff + 2 * 32768, xs, wpack + woff + 3 * 32768,
                bl_rs + D, b_p + D, 0.5f, 0, nullptr, xs_out, NS, 0);
    cudaStreamWaitEvent(0, evH2, 0);
    agg_csr<<<(NS * 32 + 255) / 256, 256>>>(h, rp_prec, col_prec, NS, 1, 0.5f, xs_out);

    // ---------- join all branches back to stream 0 ----------
    cudaStreamWaitEvent(0, evDone1, 0);
}